// round 5
// baseline (speedup 1.0000x reference)
#include <cuda_runtime.h>
#include <cuda_bf16.h>
#include <cfloat>
#include <cstdint>

#define BATCH 4
#define LSEQ 1024
#define NHEADS 32
#define NKV 8
#define HDIM 128
#define SAMPLE_Q 128
#define KEEP 512
// SCALE * log2(e): softmax in exp2 domain
#define SCALE_L2 0.12751744054648072f

#define QSTR 132   // Q/K row-major stride (uint32): a/b-frag loads map to bank 4g+t (conflict-free)
#define VSTR 136   // V stride: b-frag loads map to bank 8t+g (conflict-free)
#define PSTR 68    // P stride: a-frag loads conflict-free; stores 2-way (acceptable)

// ---------------- device scratch ----------------
__device__ float2 g_ml[BATCH * NHEADS * SAMPLE_Q];
__device__ float  g_part[BATCH * NHEADS * LSEQ];
__device__ float  g_imp[BATCH * LSEQ];
__device__ int    g_keep[BATCH * KEEP];

__device__ __forceinline__ uint32_t f2tf(float x) {
    uint32_t r; asm("cvt.rna.tf32.f32 %0, %1;" : "=r"(r) : "f"(x)); return r;
}
__device__ __forceinline__ float ex2f(float x) {
    float y; asm("ex2.approx.f32 %0, %1;" : "=f"(y) : "f"(x)); return y;
}
__device__ __forceinline__ void mma8(float* c, const uint32_t* a, const uint32_t* b) {
    asm volatile("mma.sync.aligned.m16n8k8.row.col.f32.tf32.tf32.f32 "
                 "{%0,%1,%2,%3}, {%4,%5,%6,%7}, {%8,%9}, {%0,%1,%2,%3};"
                 : "+f"(c[0]), "+f"(c[1]), "+f"(c[2]), "+f"(c[3])
                 : "r"(a[0]), "r"(a[1]), "r"(a[2]), "r"(a[3]), "r"(b[0]), "r"(b[1]));
}

// ---------------- cache passthrough (skip rows scatter will overwrite) ----------------
__global__ void copy_caches_kernel(const float4* __restrict__ kc, const float4* __restrict__ vc,
                                   float4* __restrict__ kco, float4* __restrict__ vco) {
    size_t i = (size_t)blockIdx.x * blockDim.x + threadIdx.x;   // 2,097,152
    int row = (int)(i >> 5);                                    // cache row (1024 floats = 32 float4... actually 32/ row of 128? row = i/(NKV*HDIM/4)=i/256) 
    row = (int)(i >> 8);                                        // 1024 floats per row = 256 float4
    bool skip = (row < 4096) && ((row & 1023) < 512);           // overwritten by scatter
    if (!skip) {
        kco[i] = kc[i];
        vco[i] = vc[i];
    }
}

// ---------------- main flash attention: tf32 mma.sync, 4 warps x 32 q-rows ----------------
struct AttnSmem {
    uint32_t qs[128 * QSTR];   // Q tile tf32 [qrow][d], pre-scaled by SCALE_L2
    uint32_t ks[64 * QSTR];    // K tile tf32 [krow][d]
    uint32_t vs[64 * VSTR];    // V tile tf32 [krow][d]
    uint32_t ps[128 * PSTR];   // P tile tf32 [qrow][kcol]
};

__global__ void __launch_bounds__(128, 1)
attn_kernel(const float* __restrict__ q, const float* __restrict__ k,
            const float* __restrict__ v, float* __restrict__ o)
{
    extern __shared__ char raw[];
    AttnSmem& sm = *reinterpret_cast<AttnSmem*>(raw);

    const int qt = 7 - blockIdx.x;      // long CTAs first
    const int h  = blockIdx.y;
    const int b  = blockIdx.z;
    const int kvh = h >> 2;
    const int tid = threadIdx.x;        // 128
    const int w = tid >> 5, lane = tid & 31;
    const int g = lane >> 2, t = lane & 3;
    const int qb = w * 32;              // warp's 32 q-rows

    // ---- stage Q (pre-scaled, tf32) ----
    {
        const float* qg = q + ((size_t)(b * LSEQ + qt * 128 + qb) * NHEADS + h) * HDIM;
        #pragma unroll 8
        for (int r = 0; r < 32; ++r) {
            float4 f = *(const float4*)(qg + (size_t)r * NHEADS * HDIM + lane * 4);
            uint32_t* d = &sm.qs[(qb + r) * QSTR + lane * 4];
            d[0] = f2tf(f.x * SCALE_L2); d[1] = f2tf(f.y * SCALE_L2);
            d[2] = f2tf(f.z * SCALE_L2); d[3] = f2tf(f.w * SCALE_L2);
        }
    }

    float oacc[2][16][4];
    #pragma unroll
    for (int mt = 0; mt < 2; ++mt)
        #pragma unroll
        for (int nf = 0; nf < 16; ++nf)
            #pragma unroll
            for (int j = 0; j < 4; ++j) oacc[mt][nf][j] = 0.f;
    float m_[4] = {-FLT_MAX, -FLT_MAX, -FLT_MAX, -FLT_MAX};
    float l_[4] = {0.f, 0.f, 0.f, 0.f};

    const int nkt = 2 * qt + 2;
    for (int kt = 0; kt < nkt; ++kt) {
        __syncthreads();
        // ---- stage K,V (warp w: rows w*16..w*16+15) ----
        {
            const float* kg = k + ((size_t)(b * LSEQ + kt * 64 + w * 16) * NKV + kvh) * HDIM;
            const float* vg = v + ((size_t)(b * LSEQ + kt * 64 + w * 16) * NKV + kvh) * HDIM;
            #pragma unroll 4
            for (int r = 0; r < 16; ++r) {
                float4 f = *(const float4*)(kg + (size_t)r * NKV * HDIM + lane * 4);
                uint32_t* d = &sm.ks[(w * 16 + r) * QSTR + lane * 4];
                d[0] = f2tf(f.x); d[1] = f2tf(f.y); d[2] = f2tf(f.z); d[3] = f2tf(f.w);
                float4 fv = *(const float4*)(vg + (size_t)r * NKV * HDIM + lane * 4);
                uint32_t* dv = &sm.vs[(w * 16 + r) * VSTR + lane * 4];
                dv[0] = f2tf(fv.x); dv[1] = f2tf(fv.y); dv[2] = f2tf(fv.z); dv[3] = f2tf(fv.w);
            }
        }
        __syncthreads();

        // ---- S = Q K^T (2 m-tiles per warp) ----
        float s[2][8][4];
        #pragma unroll
        for (int mt = 0; mt < 2; ++mt)
            #pragma unroll
            for (int nf = 0; nf < 8; ++nf)
                #pragma unroll
                for (int j = 0; j < 4; ++j) s[mt][nf][j] = 0.f;

        #pragma unroll
        for (int ks = 0; ks < 16; ++ks) {
            uint32_t a[2][4];
            #pragma unroll
            for (int mt = 0; mt < 2; ++mt) {
                const uint32_t* q0 = &sm.qs[(qb + mt * 16 + g) * QSTR + ks * 8 + t];
                const uint32_t* q1 = &sm.qs[(qb + mt * 16 + g + 8) * QSTR + ks * 8 + t];
                a[mt][0] = q0[0]; a[mt][1] = q1[0]; a[mt][2] = q0[4]; a[mt][3] = q1[4];
            }
            #pragma unroll
            for (int nf = 0; nf < 8; ++nf) {
                uint32_t bf[2];
                const uint32_t* kr = &sm.ks[(nf * 8 + g) * QSTR + ks * 8 + t];
                bf[0] = kr[0]; bf[1] = kr[4];
                mma8(s[0][nf], a[0], bf);
                mma8(s[1][nf], a[1], bf);
            }
        }

        if (kt >= 2 * qt) {   // causal mask (log2-domain logits; -1e30 -> ex2 gives 0)
            #pragma unroll
            for (int mt = 0; mt < 2; ++mt) {
                int r0 = qt * 128 + qb + mt * 16 + g, r1 = r0 + 8;
                #pragma unroll
                for (int nf = 0; nf < 8; ++nf) {
                    int c0 = kt * 64 + nf * 8 + 2 * t, c1 = c0 + 1;
                    if (c0 > r0) s[mt][nf][0] = -1e30f;
                    if (c1 > r0) s[mt][nf][1] = -1e30f;
                    if (c0 > r1) s[mt][nf][2] = -1e30f;
                    if (c1 > r1) s[mt][nf][3] = -1e30f;
                }
            }
        }

        // ---- online softmax (exp2 domain) ----
        #pragma unroll
        for (int mt = 0; mt < 2; ++mt) {
            float mx0 = -FLT_MAX, mx1 = -FLT_MAX;
            #pragma unroll
            for (int nf = 0; nf < 8; ++nf) {
                mx0 = fmaxf(mx0, fmaxf(s[mt][nf][0], s[mt][nf][1]));
                mx1 = fmaxf(mx1, fmaxf(s[mt][nf][2], s[mt][nf][3]));
            }
            mx0 = fmaxf(mx0, __shfl_xor_sync(0xffffffffu, mx0, 1));
            mx0 = fmaxf(mx0, __shfl_xor_sync(0xffffffffu, mx0, 2));
            mx1 = fmaxf(mx1, __shfl_xor_sync(0xffffffffu, mx1, 1));
            mx1 = fmaxf(mx1, __shfl_xor_sync(0xffffffffu, mx1, 2));
            float mn0 = fmaxf(m_[mt * 2], mx0), mn1 = fmaxf(m_[mt * 2 + 1], mx1);
            float cf0 = ex2f(m_[mt * 2] - mn0), cf1 = ex2f(m_[mt * 2 + 1] - mn1);
            float sum0 = 0.f, sum1 = 0.f;
            #pragma unroll
            for (int nf = 0; nf < 8; ++nf) {
                float p00 = ex2f(s[mt][nf][0] - mn0);
                float p01 = ex2f(s[mt][nf][1] - mn0);
                float p10 = ex2f(s[mt][nf][2] - mn1);
                float p11 = ex2f(s[mt][nf][3] - mn1);
                sum0 += p00 + p01; sum1 += p10 + p11;
                *(uint2*)&sm.ps[(qb + mt * 16 + g) * PSTR + nf * 8 + 2 * t]     = make_uint2(f2tf(p00), f2tf(p01));
                *(uint2*)&sm.ps[(qb + mt * 16 + g + 8) * PSTR + nf * 8 + 2 * t] = make_uint2(f2tf(p10), f2tf(p11));
            }
            sum0 += __shfl_xor_sync(0xffffffffu, sum0, 1);
            sum0 += __shfl_xor_sync(0xffffffffu, sum0, 2);
            sum1 += __shfl_xor_sync(0xffffffffu, sum1, 1);
            sum1 += __shfl_xor_sync(0xffffffffu, sum1, 2);
            l_[mt * 2]     = l_[mt * 2] * cf0 + sum0;
            l_[mt * 2 + 1] = l_[mt * 2 + 1] * cf1 + sum1;
            m_[mt * 2] = mn0; m_[mt * 2 + 1] = mn1;
            #pragma unroll
            for (int nf = 0; nf < 16; ++nf) {
                oacc[mt][nf][0] *= cf0; oacc[mt][nf][1] *= cf0;
                oacc[mt][nf][2] *= cf1; oacc[mt][nf][3] *= cf1;
            }
        }
        __syncwarp();   // P visible to quad-mates

        // ---- O += P V ----
        #pragma unroll
        for (int ks2 = 0; ks2 < 8; ++ks2) {
            uint32_t a0[4], a1[4];
            {
                const uint32_t* p00 = &sm.ps[(qb + g) * PSTR + ks2 * 8 + t];
                const uint32_t* p01 = &sm.ps[(qb + g + 8) * PSTR + ks2 * 8 + t];
                const uint32_t* p10 = &sm.ps[(qb + 16 + g) * PSTR + ks2 * 8 + t];
                const uint32_t* p11 = &sm.ps[(qb + 24 + g) * PSTR + ks2 * 8 + t];
                a0[0] = p00[0]; a0[1] = p01[0]; a0[2] = p00[4]; a0[3] = p01[4];
                a1[0] = p10[0]; a1[1] = p11[0]; a1[2] = p10[4]; a1[3] = p11[4];
            }
            #pragma unroll
            for (int nf = 0; nf < 16; ++nf) {
                uint32_t bf[2];
                bf[0] = sm.vs[(ks2 * 8 + t) * VSTR + nf * 8 + g];
                bf[1] = sm.vs[(ks2 * 8 + t + 4) * VSTR + nf * 8 + g];
                mma8(oacc[0][nf], a0, bf);
                mma8(oacc[1][nf], a1, bf);
            }
        }
    }

    // ---- epilogue ----
    #pragma unroll
    for (int mt = 0; mt < 2; ++mt) {
        float i0 = 1.f / l_[mt * 2], i1 = 1.f / l_[mt * 2 + 1];
        int r0 = qt * 128 + qb + mt * 16 + g;
        float* o0 = o + ((size_t)(b * LSEQ + r0) * NHEADS + h) * HDIM;
        float* o1 = o0 + (size_t)8 * NHEADS * HDIM;
        #pragma unroll
        for (int nf = 0; nf < 16; ++nf) {
            *(float2*)&o0[nf * 8 + 2 * t] = make_float2(oacc[mt][nf][0] * i0, oacc[mt][nf][1] * i0);
            *(float2*)&o1[nf * 8 + 2 * t] = make_float2(oacc[mt][nf][2] * i1, oacc[mt][nf][3] * i1);
        }
    }
    if (qt == 7 && t == 0) {
        int base_i = (b * NHEADS + h) * SAMPLE_Q;
        g_ml[base_i + qb + g]      = make_float2(m_[0], l_[0]);
        g_ml[base_i + qb + g + 8]  = make_float2(m_[1], l_[1]);
        g_ml[base_i + qb + g + 16] = make_float2(m_[2], l_[2]);
        g_ml[base_i + qb + g + 24] = make_float2(m_[3], l_[3]);
    }
}

// ---------------- SnapKV sample scores (tf32 mma, exp2 domain) ----------------
struct SampSmem {
    uint32_t qs[128 * QSTR];
    uint32_t ks[64 * QSTR];
    float colpart[8][64];
};

__global__ void __launch_bounds__(256)
sample_kernel(const float* __restrict__ q, const float* __restrict__ k)
{
    extern __shared__ char raw[];
    SampSmem& sm = *reinterpret_cast<SampSmem*>(raw);

    const int kt = blockIdx.x;
    const int bh = blockIdx.y;
    const int b = bh >> 5, h = bh & 31, kvh = h >> 2;
    const int tid = threadIdx.x;
    const int w = tid >> 5, lane = tid & 31;
    const int g = lane >> 2, t = lane & 3;
    const int qb = w * 16;

    {
        const float* qg = q + ((size_t)(b * LSEQ + (LSEQ - SAMPLE_Q) + qb) * NHEADS + h) * HDIM;
        #pragma unroll 4
        for (int r = 0; r < 16; ++r) {
            float4 f = *(const float4*)(qg + (size_t)r * NHEADS * HDIM + lane * 4);
            uint32_t* d = &sm.qs[(qb + r) * QSTR + lane * 4];
            d[0] = f2tf(f.x * SCALE_L2); d[1] = f2tf(f.y * SCALE_L2);
            d[2] = f2tf(f.z * SCALE_L2); d[3] = f2tf(f.w * SCALE_L2);
        }
        const float* kg = k + ((size_t)(b * LSEQ + kt * 64 + w * 8) * NKV + kvh) * HDIM;
        #pragma unroll
        for (int r = 0; r < 8; ++r) {
            float4 f = *(const float4*)(kg + (size_t)r * NKV * HDIM + lane * 4);
            uint32_t* d = &sm.ks[(w * 8 + r) * QSTR + lane * 4];
            d[0] = f2tf(f.x); d[1] = f2tf(f.y); d[2] = f2tf(f.z); d[3] = f2tf(f.w);
        }
    }
    __syncthreads();

    float s[8][4];
    #pragma unroll
    for (int nf = 0; nf < 8; ++nf)
        #pragma unroll
        for (int j = 0; j < 4; ++j) s[nf][j] = 0.f;

    #pragma unroll
    for (int ks = 0; ks < 16; ++ks) {
        uint32_t a[4];
        const uint32_t* q0 = &sm.qs[(qb + g) * QSTR + ks * 8 + t];
        const uint32_t* q1 = &sm.qs[(qb + g + 8) * QSTR + ks * 8 + t];
        a[0] = q0[0]; a[1] = q1[0]; a[2] = q0[4]; a[3] = q1[4];
        #pragma unroll
        for (int nf = 0; nf < 8; ++nf) {
            uint32_t bf[2];
            const uint32_t* kr = &sm.ks[(nf * 8 + g) * QSTR + ks * 8 + t];
            bf[0] = kr[0]; bf[1] = kr[4];
            mma8(s[nf], a, bf);
        }
    }

    float2 ml0 = g_ml[bh * SAMPLE_Q + qb + g];
    float2 ml1 = g_ml[bh * SAMPLE_Q + qb + g + 8];
    float il0 = 1.f / ml0.y, il1 = 1.f / ml1.y;
    int r0 = (LSEQ - SAMPLE_Q) + qb + g, r1 = r0 + 8;

    float cp[16];
    #pragma unroll
    for (int j = 0; j < 16; ++j) cp[j] = 0.f;
    #pragma unroll
    for (int nf = 0; nf < 8; ++nf) {
        int c0 = kt * 64 + nf * 8 + 2 * t, c1 = c0 + 1;
        float p00 = (c0 <= r0) ? ex2f(s[nf][0] - ml0.x) * il0 : 0.f;
        float p01 = (c1 <= r0) ? ex2f(s[nf][1] - ml0.x) * il0 : 0.f;
        float p10 = (c0 <= r1) ? ex2f(s[nf][2] - ml1.x) * il1 : 0.f;
        float p11 = (c1 <= r1) ? ex2f(s[nf][3] - ml1.x) * il1 : 0.f;
        cp[nf * 2]     += p00 + p10;
        cp[nf * 2 + 1] += p01 + p11;
    }
    #pragma unroll
    for (int d = 4; d < 32; d <<= 1)
        #pragma unroll
        for (int j = 0; j < 16; ++j)
            cp[j] += __shfl_xor_sync(0xffffffffu, cp[j], d);
    if (g == 0) {
        #pragma unroll
        for (int nf = 0; nf < 8; ++nf) {
            sm.colpart[w][nf * 8 + 2 * t]     = cp[nf * 2];
            sm.colpart[w][nf * 8 + 2 * t + 1] = cp[nf * 2 + 1];
        }
    }
    __syncthreads();
    if (tid < 64) {
        float ssum = 0.f;
        #pragma unroll
        for (int ww = 0; ww < 8; ++ww) ssum += sm.colpart[ww][tid];
        g_part[(size_t)bh * LSEQ + kt * 64 + tid] = ssum;
    }
}

// ---------------- deterministic reduce over heads ----------------
__global__ void reduce_kernel() {
    int idx = blockIdx.x * 256 + threadIdx.x;   // 4096
    int b = idx >> 10, kk = idx & 1023;
    float s = 0.f;
    #pragma unroll
    for (int h = 0; h < NHEADS; ++h)
        s += g_part[(size_t)(b * NHEADS + h) * LSEQ + kk];
    g_imp[idx] = s;
}

// ---------------- exact top-512 + ascending order ----------------
__global__ void topk_kernel() {
    const int b = blockIdx.x;
    const int tid = threadIdx.x;                // 1024
    __shared__ float vals[LSEQ];
    __shared__ unsigned flags[32];
    vals[tid] = g_imp[b * LSEQ + tid];
    __syncthreads();
    float v = vals[tid];
    int cnt = 0;
    for (int j = 0; j < LSEQ; ++j) {
        float wv = vals[j];
        cnt += (wv > v) || (wv == v && j < tid);
    }
    bool kept = (cnt < KEEP);
    unsigned bal = __ballot_sync(0xffffffffu, kept);
    if ((tid & 31) == 0) flags[tid >> 5] = bal;
    __syncthreads();
    if (kept) {
        int wq = tid >> 5;
        int pos = 0;
        for (int tq = 0; tq < wq; ++tq) pos += __popc(flags[tq]);
        pos += __popc(flags[wq] & ((1u << (tid & 31)) - 1u));
        g_keep[b * KEEP + pos] = tid;
    }
}

// ---------------- gather kept tokens, scatter to cache slots ----------------
__global__ void scatter_kernel(const float* __restrict__ k, const float* __restrict__ v,
                               const int* __restrict__ slot_map,
                               float* __restrict__ kco, float* __restrict__ vco) {
    int r = blockIdx.x;                         // 2048 rows
    int b = r >> 9, j = r & 511;
    int src = b * LSEQ + g_keep[b * KEEP + j];
    int dst = slot_map[b * LSEQ + j];
    const float4* ks = (const float4*)(k + (size_t)src * (NKV * HDIM));
    const float4* vs = (const float4*)(v + (size_t)src * (NKV * HDIM));
    float4* kd = (float4*)(kco + (size_t)dst * (NKV * HDIM));
    float4* vd = (float4*)(vco + (size_t)dst * (NKV * HDIM));
    kd[threadIdx.x] = ks[threadIdx.x];
    vd[threadIdx.x] = vs[threadIdx.x];
}

// ---------------- launch ----------------
extern "C" void kernel_launch(void* const* d_in, const int* in_sizes, int n_in,
                              void* d_out, int out_size) {
    const float* q  = (const float*)d_in[0];
    const float* k  = (const float*)d_in[1];
    const float* v  = (const float*)d_in[2];
    const float* kc = (const float*)d_in[3];
    const float* vc = (const float*)d_in[4];
    const int* slot = (const int*)d_in[5];

    float* o   = (float*)d_out;
    float* kco = o + (size_t)BATCH * LSEQ * NHEADS * HDIM;
    float* vco = kco + (size_t)8192 * (NKV * HDIM);

    cudaFuncSetAttribute(attn_kernel, cudaFuncAttributeMaxDynamicSharedMemorySize, (int)sizeof(AttnSmem));
    cudaFuncSetAttribute(sample_kernel, cudaFuncAttributeMaxDynamicSharedMemorySize, (int)sizeof(SampSmem));

    copy_caches_kernel<<<8192, 256>>>((const float4*)kc, (const float4*)vc,
                                      (float4*)kco, (float4*)vco);
    attn_kernel<<<dim3(8, NHEADS, BATCH), 128, sizeof(AttnSmem)>>>(q, k, v, o);
    sample_kernel<<<dim3(16, BATCH * NHEADS), 256, sizeof(SampSmem)>>>(q, k);
    reduce_kernel<<<16, 256>>>();
    topk_kernel<<<BATCH, 1024>>>();
    scatter_kernel<<<2048, 256>>>(k, v, slot, kco, vco);
}

// round 6
// speedup vs baseline: 1.0710x; 1.0710x over previous
#include <cuda_runtime.h>
#include <cuda_bf16.h>
#include <cfloat>
#include <cstdint>

#define BATCH 4
#define LSEQ 1024
#define NHEADS 32
#define NKV 8
#define HDIM 128
#define SAMPLE_Q 128
#define KEEP 512
// SCALE * log2(e): softmax in exp2 domain
#define SCALE_L2 0.12751744054648072f

#define QSTR 132   // Q/K row-major stride (uint32): frag loads conflict-free
#define VSTR 136   // V stride: b-frag loads conflict-free
#define PSTR 68    // P stride: a-frag loads conflict-free

// ---------------- device scratch ----------------
__device__ float2 g_ml[BATCH * NHEADS * SAMPLE_Q];
__device__ float  g_part[BATCH * NHEADS * LSEQ];
__device__ float  g_imp[BATCH * LSEQ];
__device__ int    g_keep[BATCH * KEEP];

__device__ __forceinline__ uint32_t f2tf(float x) {
    uint32_t r; asm("cvt.rna.tf32.f32 %0, %1;" : "=r"(r) : "f"(x)); return r;
}
__device__ __forceinline__ float ex2f(float x) {
    float y; asm("ex2.approx.f32 %0, %1;" : "=f"(y) : "f"(x)); return y;
}
__device__ __forceinline__ void mma8(float* c, const uint32_t* a, const uint32_t* b) {
    asm volatile("mma.sync.aligned.m16n8k8.row.col.f32.tf32.tf32.f32 "
                 "{%0,%1,%2,%3}, {%4,%5,%6,%7}, {%8,%9}, {%0,%1,%2,%3};"
                 : "+f"(c[0]), "+f"(c[1]), "+f"(c[2]), "+f"(c[3])
                 : "r"(a[0]), "r"(a[1]), "r"(a[2]), "r"(a[3]), "r"(b[0]), "r"(b[1]));
}

// ---------------- cache passthrough (skip rows scatter overwrites) ----------------
__global__ void copy_caches_kernel(const float4* __restrict__ kc, const float4* __restrict__ vc,
                                   float4* __restrict__ kco, float4* __restrict__ vco) {
    size_t i = (size_t)blockIdx.x * blockDim.x + threadIdx.x;   // 2,097,152 float4
    int row = (int)(i >> 8);                                    // 256 float4 per cache row
    bool skip = (row < BATCH * LSEQ) && ((row & (LSEQ - 1)) < KEEP);  // scatter targets
    if (!skip) {
        kco[i] = kc[i];
        vco[i] = vc[i];
    }
}

// ---------------- main flash attention: tf32 mma.sync, 8 warps x 16 q-rows ----------------
struct AttnSmem {
    uint32_t qs[128 * QSTR];   // Q tile tf32 [qrow][d], pre-scaled by SCALE_L2
    uint32_t ks[64 * QSTR];    // K tile tf32 [krow][d]
    uint32_t vs[64 * VSTR];    // V tile tf32 [krow][d]
    uint32_t ps[128 * PSTR];   // P tile tf32 [qrow][kcol]
};

__global__ void __launch_bounds__(256, 1)
attn_kernel(const float* __restrict__ q, const float* __restrict__ k,
            const float* __restrict__ v, float* __restrict__ o)
{
    extern __shared__ char raw[];
    AttnSmem& sm = *reinterpret_cast<AttnSmem*>(raw);

    const int qt = 7 - blockIdx.x;      // long CTAs first
    const int h  = blockIdx.y;
    const int b  = blockIdx.z;
    const int kvh = h >> 2;
    const int tid = threadIdx.x;
    const int w = tid >> 5, lane = tid & 31;
    const int g = lane >> 2, t = lane & 3;
    const int qb = w * 16;              // warp's 16 q-rows

    // ---- stage Q (pre-scaled by SCALE*log2e) ----
    {
        const float* qg = q + ((size_t)(b * LSEQ + qt * 128 + qb) * NHEADS + h) * HDIM;
        #pragma unroll 4
        for (int r = 0; r < 16; ++r) {
            float4 f = *(const float4*)(qg + (size_t)r * NHEADS * HDIM + lane * 4);
            uint32_t* d = &sm.qs[(qb + r) * QSTR + lane * 4];
            d[0] = f2tf(f.x * SCALE_L2); d[1] = f2tf(f.y * SCALE_L2);
            d[2] = f2tf(f.z * SCALE_L2); d[3] = f2tf(f.w * SCALE_L2);
        }
    }

    float oacc[16][4];
    #pragma unroll
    for (int nf = 0; nf < 16; ++nf)
        #pragma unroll
        for (int j = 0; j < 4; ++j) oacc[nf][j] = 0.f;
    float m0 = -FLT_MAX, m1 = -FLT_MAX, l0 = 0.f, l1 = 0.f;

    const int row_hi = qt * 128 + qb + 15;     // warp's highest q-row
    const int nkt = 2 * qt + 2;

    for (int kt = 0; kt < nkt; ++kt) {
        __syncthreads();
        // ---- stage K,V (warp w: rows w*8..w*8+7) ----
        {
            const float* kg = k + ((size_t)(b * LSEQ + kt * 64 + w * 8) * NKV + kvh) * HDIM;
            const float* vg = v + ((size_t)(b * LSEQ + kt * 64 + w * 8) * NKV + kvh) * HDIM;
            #pragma unroll
            for (int r = 0; r < 8; ++r) {
                float4 f = *(const float4*)(kg + (size_t)r * NKV * HDIM + lane * 4);
                uint32_t* d = &sm.ks[(w * 8 + r) * QSTR + lane * 4];
                d[0] = f2tf(f.x); d[1] = f2tf(f.y); d[2] = f2tf(f.z); d[3] = f2tf(f.w);
                float4 fv = *(const float4*)(vg + (size_t)r * NKV * HDIM + lane * 4);
                uint32_t* dv = &sm.vs[(w * 8 + r) * VSTR + lane * 4];
                dv[0] = f2tf(fv.x); dv[1] = f2tf(fv.y); dv[2] = f2tf(fv.z); dv[3] = f2tf(fv.w);
            }
        }
        __syncthreads();

        // per-warp active column-tile bound (diagonal tiles only)
        const bool diag = (kt >= 2 * qt);
        int nf_hi = 8;
        if (diag) {
            int d0 = row_hi - kt * 64;           // max allowed col offset
            nf_hi = (d0 < 0) ? 0 : ((d0 >> 3) + 1);
            if (nf_hi > 8) nf_hi = 8;
        }
        if (nf_hi == 0) continue;                // fully masked: nothing changes

        // ---- S = Q K^T (only active nf tiles) ----
        float s[8][4];
        #pragma unroll
        for (int nf = 0; nf < 8; ++nf)
            #pragma unroll
            for (int j = 0; j < 4; ++j) s[nf][j] = 0.f;

        #pragma unroll
        for (int ks = 0; ks < 16; ++ks) {
            uint32_t a[4];
            const uint32_t* q0 = &sm.qs[(qb + g) * QSTR + ks * 8 + t];
            const uint32_t* q1 = &sm.qs[(qb + g + 8) * QSTR + ks * 8 + t];
            a[0] = q0[0]; a[1] = q1[0]; a[2] = q0[4]; a[3] = q1[4];
            #pragma unroll
            for (int nf = 0; nf < 8; ++nf) {
                if (nf < nf_hi) {
                    uint32_t bf[2];
                    const uint32_t* kr = &sm.ks[(nf * 8 + g) * QSTR + ks * 8 + t];
                    bf[0] = kr[0]; bf[1] = kr[4];
                    mma8(s[nf], a, bf);
                }
            }
        }

        if (diag) {   // causal mask within active tiles
            int r0 = qt * 128 + qb + g, r1 = r0 + 8;
            #pragma unroll
            for (int nf = 0; nf < 8; ++nf) {
                if (nf < nf_hi) {
                    int c0 = kt * 64 + nf * 8 + 2 * t, c1 = c0 + 1;
                    if (c0 > r0) s[nf][0] = -1e30f;
                    if (c1 > r0) s[nf][1] = -1e30f;
                    if (c0 > r1) s[nf][2] = -1e30f;
                    if (c1 > r1) s[nf][3] = -1e30f;
                }
            }
        }

        // ---- online softmax (exp2 domain) over active tiles ----
        float mx0 = -FLT_MAX, mx1 = -FLT_MAX;
        #pragma unroll
        for (int nf = 0; nf < 8; ++nf) {
            if (nf < nf_hi) {
                mx0 = fmaxf(mx0, fmaxf(s[nf][0], s[nf][1]));
                mx1 = fmaxf(mx1, fmaxf(s[nf][2], s[nf][3]));
            }
        }
        mx0 = fmaxf(mx0, __shfl_xor_sync(0xffffffffu, mx0, 1));
        mx0 = fmaxf(mx0, __shfl_xor_sync(0xffffffffu, mx0, 2));
        mx1 = fmaxf(mx1, __shfl_xor_sync(0xffffffffu, mx1, 1));
        mx1 = fmaxf(mx1, __shfl_xor_sync(0xffffffffu, mx1, 2));
        float mn0 = fmaxf(m0, mx0), mn1 = fmaxf(m1, mx1);
        float cf0 = ex2f(m0 - mn0), cf1 = ex2f(m1 - mn1);
        float sum0 = 0.f, sum1 = 0.f;
        #pragma unroll
        for (int nf = 0; nf < 8; ++nf) {
            if (nf < nf_hi) {
                float p00 = ex2f(s[nf][0] - mn0);
                float p01 = ex2f(s[nf][1] - mn0);
                float p10 = ex2f(s[nf][2] - mn1);
                float p11 = ex2f(s[nf][3] - mn1);
                sum0 += p00 + p01; sum1 += p10 + p11;
                *(uint2*)&sm.ps[(qb + g) * PSTR + nf * 8 + 2 * t]     = make_uint2(f2tf(p00), f2tf(p01));
                *(uint2*)&sm.ps[(qb + g + 8) * PSTR + nf * 8 + 2 * t] = make_uint2(f2tf(p10), f2tf(p11));
            }
        }
        sum0 += __shfl_xor_sync(0xffffffffu, sum0, 1);
        sum0 += __shfl_xor_sync(0xffffffffu, sum0, 2);
        sum1 += __shfl_xor_sync(0xffffffffu, sum1, 1);
        sum1 += __shfl_xor_sync(0xffffffffu, sum1, 2);
        l0 = l0 * cf0 + sum0; l1 = l1 * cf1 + sum1;
        m0 = mn0; m1 = mn1;
        #pragma unroll
        for (int nf = 0; nf < 16; ++nf) {
            oacc[nf][0] *= cf0; oacc[nf][1] *= cf0;
            oacc[nf][2] *= cf1; oacc[nf][3] *= cf1;
        }
        __syncwarp();   // P stores visible to quad-mates

        // ---- O += P V (only active k sub-tiles) ----
        #pragma unroll
        for (int ks2 = 0; ks2 < 8; ++ks2) {
            if (ks2 < nf_hi) {
                uint32_t a[4];
                const uint32_t* p0 = &sm.ps[(qb + g) * PSTR + ks2 * 8 + t];
                const uint32_t* p1 = &sm.ps[(qb + g + 8) * PSTR + ks2 * 8 + t];
                a[0] = p0[0]; a[1] = p1[0]; a[2] = p0[4]; a[3] = p1[4];
                #pragma unroll
                for (int nf = 0; nf < 16; ++nf) {
                    uint32_t bf[2];
                    bf[0] = sm.vs[(ks2 * 8 + t) * VSTR + nf * 8 + g];
                    bf[1] = sm.vs[(ks2 * 8 + t + 4) * VSTR + nf * 8 + g];
                    mma8(oacc[nf], a, bf);
                }
            }
        }
    }

    // ---- epilogue ----
    float inv0 = 1.f / l0, inv1 = 1.f / l1;
    int r0 = qt * 128 + qb + g;
    float* o0 = o + ((size_t)(b * LSEQ + r0) * NHEADS + h) * HDIM;
    float* o1 = o0 + (size_t)8 * NHEADS * HDIM;
    #pragma unroll
    for (int nf = 0; nf < 16; ++nf) {
        *(float2*)&o0[nf * 8 + 2 * t] = make_float2(oacc[nf][0] * inv0, oacc[nf][1] * inv0);
        *(float2*)&o1[nf * 8 + 2 * t] = make_float2(oacc[nf][2] * inv1, oacc[nf][3] * inv1);
    }
    if (qt == 7 && t == 0) {
        g_ml[(b * NHEADS + h) * SAMPLE_Q + qb + g]     = make_float2(m0, l0);
        g_ml[(b * NHEADS + h) * SAMPLE_Q + qb + g + 8] = make_float2(m1, l1);
    }
}

// ---------------- SnapKV sample scores (tf32 mma, exp2 domain) ----------------
struct SampSmem {
    uint32_t qs[128 * QSTR];
    uint32_t ks[64 * QSTR];
    float colpart[8][64];
};

__global__ void __launch_bounds__(256)
sample_kernel(const float* __restrict__ q, const float* __restrict__ k)
{
    extern __shared__ char raw[];
    SampSmem& sm = *reinterpret_cast<SampSmem*>(raw);

    const int kt = blockIdx.x;
    const int bh = blockIdx.y;
    const int b = bh >> 5, h = bh & 31, kvh = h >> 2;
    const int tid = threadIdx.x;
    const int w = tid >> 5, lane = tid & 31;
    const int g = lane >> 2, t = lane & 3;
    const int qb = w * 16;

    {
        const float* qg = q + ((size_t)(b * LSEQ + (LSEQ - SAMPLE_Q) + qb) * NHEADS + h) * HDIM;
        #pragma unroll 4
        for (int r = 0; r < 16; ++r) {
            float4 f = *(const float4*)(qg + (size_t)r * NHEADS * HDIM + lane * 4);
            uint32_t* d = &sm.qs[(qb + r) * QSTR + lane * 4];
            d[0] = f2tf(f.x * SCALE_L2); d[1] = f2tf(f.y * SCALE_L2);
            d[2] = f2tf(f.z * SCALE_L2); d[3] = f2tf(f.w * SCALE_L2);
        }
        const float* kg = k + ((size_t)(b * LSEQ + kt * 64 + w * 8) * NKV + kvh) * HDIM;
        #pragma unroll
        for (int r = 0; r < 8; ++r) {
            float4 f = *(const float4*)(kg + (size_t)r * NKV * HDIM + lane * 4);
            uint32_t* d = &sm.ks[(w * 8 + r) * QSTR + lane * 4];
            d[0] = f2tf(f.x); d[1] = f2tf(f.y); d[2] = f2tf(f.z); d[3] = f2tf(f.w);
        }
    }
    __syncthreads();

    float s[8][4];
    #pragma unroll
    for (int nf = 0; nf < 8; ++nf)
        #pragma unroll
        for (int j = 0; j < 4; ++j) s[nf][j] = 0.f;

    #pragma unroll
    for (int ks = 0; ks < 16; ++ks) {
        uint32_t a[4];
        const uint32_t* q0 = &sm.qs[(qb + g) * QSTR + ks * 8 + t];
        const uint32_t* q1 = &sm.qs[(qb + g + 8) * QSTR + ks * 8 + t];
        a[0] = q0[0]; a[1] = q1[0]; a[2] = q0[4]; a[3] = q1[4];
        #pragma unroll
        for (int nf = 0; nf < 8; ++nf) {
            uint32_t bf[2];
            const uint32_t* kr = &sm.ks[(nf * 8 + g) * QSTR + ks * 8 + t];
            bf[0] = kr[0]; bf[1] = kr[4];
            mma8(s[nf], a, bf);
        }
    }

    float2 ml0 = g_ml[bh * SAMPLE_Q + qb + g];
    float2 ml1 = g_ml[bh * SAMPLE_Q + qb + g + 8];
    float il0 = 1.f / ml0.y, il1 = 1.f / ml1.y;
    int r0 = (LSEQ - SAMPLE_Q) + qb + g, r1 = r0 + 8;

    float cp[16];
    #pragma unroll
    for (int j = 0; j < 16; ++j) cp[j] = 0.f;
    #pragma unroll
    for (int nf = 0; nf < 8; ++nf) {
        int c0 = kt * 64 + nf * 8 + 2 * t, c1 = c0 + 1;
        float p00 = (c0 <= r0) ? ex2f(s[nf][0] - ml0.x) * il0 : 0.f;
        float p01 = (c1 <= r0) ? ex2f(s[nf][1] - ml0.x) * il0 : 0.f;
        float p10 = (c0 <= r1) ? ex2f(s[nf][2] - ml1.x) * il1 : 0.f;
        float p11 = (c1 <= r1) ? ex2f(s[nf][3] - ml1.x) * il1 : 0.f;
        cp[nf * 2]     += p00 + p10;
        cp[nf * 2 + 1] += p01 + p11;
    }
    #pragma unroll
    for (int d = 4; d < 32; d <<= 1)
        #pragma unroll
        for (int j = 0; j < 16; ++j)
            cp[j] += __shfl_xor_sync(0xffffffffu, cp[j], d);
    if (g == 0) {
        #pragma unroll
        for (int nf = 0; nf < 8; ++nf) {
            sm.colpart[w][nf * 8 + 2 * t]     = cp[nf * 2];
            sm.colpart[w][nf * 8 + 2 * t + 1] = cp[nf * 2 + 1];
        }
    }
    __syncthreads();
    if (tid < 64) {
        float ssum = 0.f;
        #pragma unroll
        for (int ww = 0; ww < 8; ++ww) ssum += sm.colpart[ww][tid];
        g_part[(size_t)bh * LSEQ + kt * 64 + tid] = ssum;
    }
}

// ---------------- deterministic reduce over heads ----------------
__global__ void reduce_kernel() {
    int idx = blockIdx.x * 256 + threadIdx.x;   // 4096
    int b = idx >> 10, kk = idx & 1023;
    float s = 0.f;
    #pragma unroll
    for (int h = 0; h < NHEADS; ++h)
        s += g_part[(size_t)(b * NHEADS + h) * LSEQ + kk];
    g_imp[idx] = s;
}

// ---------------- exact top-512 + ascending order ----------------
__global__ void topk_kernel() {
    const int b = blockIdx.x;
    const int tid = threadIdx.x;                // 1024
    __shared__ float vals[LSEQ];
    __shared__ unsigned flags[32];
    vals[tid] = g_imp[b * LSEQ + tid];
    __syncthreads();
    float v = vals[tid];
    int cnt = 0;
    for (int j = 0; j < LSEQ; ++j) {
        float wv = vals[j];
        cnt += (wv > v) || (wv == v && j < tid);
    }
    bool kept = (cnt < KEEP);
    unsigned bal = __ballot_sync(0xffffffffu, kept);
    if ((tid & 31) == 0) flags[tid >> 5] = bal;
    __syncthreads();
    if (kept) {
        int wq = tid >> 5;
        int pos = 0;
        for (int tq = 0; tq < wq; ++tq) pos += __popc(flags[tq]);
        pos += __popc(flags[wq] & ((1u << (tid & 31)) - 1u));
        g_keep[b * KEEP + pos] = tid;
    }
}

// ---------------- gather kept tokens, scatter to cache slots ----------------
__global__ void scatter_kernel(const float* __restrict__ k, const float* __restrict__ v,
                               const int* __restrict__ slot_map,
                               float* __restrict__ kco, float* __restrict__ vco) {
    int r = blockIdx.x;                         // 2048 rows
    int b = r >> 9, j = r & 511;
    int src = b * LSEQ + g_keep[b * KEEP + j];
    int dst = slot_map[b * LSEQ + j];
    const float4* ks = (const float4*)(k + (size_t)src * (NKV * HDIM));
    const float4* vs = (const float4*)(v + (size_t)src * (NKV * HDIM));
    float4* kd = (float4*)(kco + (size_t)dst * (NKV * HDIM));
    float4* vd = (float4*)(vco + (size_t)dst * (NKV * HDIM));
    kd[threadIdx.x] = ks[threadIdx.x];
    vd[threadIdx.x] = vs[threadIdx.x];
}

// ---------------- launch ----------------
extern "C" void kernel_launch(void* const* d_in, const int* in_sizes, int n_in,
                              void* d_out, int out_size) {
    const float* q  = (const float*)d_in[0];
    const float* k  = (const float*)d_in[1];
    const float* v  = (const float*)d_in[2];
    const float* kc = (const float*)d_in[3];
    const float* vc = (const float*)d_in[4];
    const int* slot = (const int*)d_in[5];

    float* o   = (float*)d_out;
    float* kco = o + (size_t)BATCH * LSEQ * NHEADS * HDIM;
    float* vco = kco + (size_t)8192 * (NKV * HDIM);

    cudaFuncSetAttribute(attn_kernel, cudaFuncAttributeMaxDynamicSharedMemorySize, (int)sizeof(AttnSmem));
    cudaFuncSetAttribute(sample_kernel, cudaFuncAttributeMaxDynamicSharedMemorySize, (int)sizeof(SampSmem));

    copy_caches_kernel<<<8192, 256>>>((const float4*)kc, (const float4*)vc,
                                      (float4*)kco, (float4*)vco);
    attn_kernel<<<dim3(8, NHEADS, BATCH), 256, sizeof(AttnSmem)>>>(q, k, v, o);
    sample_kernel<<<dim3(16, BATCH * NHEADS), 256, sizeof(SampSmem)>>>(q, k);
    reduce_kernel<<<16, 256>>>();
    topk_kernel<<<BATCH, 1024>>>();
    scatter_kernel<<<2048, 256>>>(k, v, slot, kco, vco);
}